// round 15
// baseline (speedup 1.0000x reference)
#include <cuda_runtime.h>
#include <math.h>

// ---------------------------------------------------------------------------
// EqAMPBC: M=41, RHO=1.0, Nmodes=2, B=131072
// OUTPUT LAYOUT (established by R14 probe, f=11/16): PLANAR —
//   out[0      .. 2B)  = real parts, (B,2) C-order: 2b+n
//   out[2B     .. 4B)  = imag parts, (B,2) C-order: 2b+n
// in_sizes / out_size are BYTE counts (established R8 vs R10).
// ---------------------------------------------------------------------------

#define MM    41
#define PP    20
#define HDIM  260
#define NB    64
#define TPB   64

struct Tables {
    short n_of_h[HDIM];
    short h_start[MM + 1];
    int   cnt;
    constexpr Tables() : n_of_h(), h_start(), cnt(0) {
        int idx = 0;
        for (int mi = 0; mi < MM; ++mi) {
            h_start[mi] = (short)idx;
            const int m = mi - PP;
            for (int n = -PP; n <= PP; ++n) {
                int mn = m * n;   if (mn  < 0) mn  = -mn;
                int mpn = m + n;  if (mpn < 0) mpn = -mpn;
                if (m != 0 && n != 0 && mn <= PP && mpn <= PP) {
                    n_of_h[idx] = (short)n;
                    ++idx;
                }
            }
        }
        h_start[MM] = (short)idx;
        cnt = idx;
    }
};
static_assert(Tables().cnt == HDIM, "HDIM mismatch with reference fwm_index");

__global__ __launch_bounds__(TPB)
void eqampbc_kernel(const float* __restrict__ x_real,  long long xr_sz,
                    const float* __restrict__ x_imag,  long long xi_sz,
                    const float* __restrict__ task_info, long long ti_sz,
                    const float* __restrict__ C00,     long long c00_sz,
                    const float* __restrict__ fwm_wr,  long long wr_sz,
                    const float* __restrict__ fwm_wi,  long long wi_sz,
                    const float* __restrict__ conv1_w, long long c1_sz,
                    const float* __restrict__ conv2_w, long long c2_sz,
                    float* __restrict__ out,           long long out_floats,
                    int B)
{
    __shared__ float4 shx[NB * MM];   // stride 164 words: conflict-free LDS.128
    __shared__ float4 shw[HDIM];
    __shared__ float2 shw12[MM];

    const int tid = threadIdx.x;
    const int b0  = blockIdx.x * NB;

    for (int h = tid; h < HDIM; h += TPB) {
        const float w0r = (h < wr_sz)        ? fwm_wr[h]        : 0.0f;
        const float w0i = (h < wi_sz)        ? fwm_wi[h]        : 0.0f;
        const float w1r = (HDIM + h < wr_sz) ? fwm_wr[HDIM + h] : 0.0f;
        const float w1i = (HDIM + h < wi_sz) ? fwm_wi[HDIM + h] : 0.0f;
        shw[h] = make_float4(w0r, w0i, w1r, w1i);
    }
    if (tid < MM) {
        const float w1 = (tid == PP || tid >= c1_sz) ? 0.0f : conv1_w[tid];
        const float w2 = (tid == PP || tid >= c2_sz) ? 0.0f : conv2_w[tid];
        shw12[tid] = make_float2(w1, w2);
    }

    {
        int rem = B - b0; if (rem > NB) rem = NB;
        int lim = rem * MM;
        const long long base = (long long)b0 * (MM * 2);
        long long mxs = xr_sz < xi_sz ? xr_sz : xi_sz;
        long long avail = (mxs - base) / 2;
        if (avail < 0) avail = 0;
        if ((long long)lim > avail) lim = (int)avail;
        for (int j = tid; j < lim; j += TPB) {
            const long long g = base + (long long)j * 2;
            shx[j] = make_float4(x_real[g], x_imag[g], x_real[g + 1], x_imag[g + 1]);
        }
        for (int j = lim + tid; j < NB * MM; j += TPB)
            shx[j] = make_float4(0.f, 0.f, 0.f, 0.f);
    }
    __syncthreads();

    const int b = b0 + tid;
    if (b >= B) return;

    const float4* __restrict__ xb = shx + tid * MM;
    constexpr Tables TB{};

    float E0r = 0.f, E0i = 0.f, E1r = 0.f, E1i = 0.f;
    float ph0 = 0.f, ph1 = 0.f;
    float c0r = 0.f, c0i = 0.f;
    float4 xp = make_float4(0.f, 0.f, 0.f, 0.f);

#pragma unroll
    for (int mi = 0; mi < MM; ++mi) {
        const float4 Em = xb[mi];
        if (mi == PP) xp = Em;

        const float2 w12 = shw12[mi];
        const float p0  = Em.x * Em.x + Em.y * Em.y;
        const float p1  = Em.z * Em.z + Em.w * Em.w;
        ph0 += w12.x * (2.0f * p0 + p1);
        ph1 += w12.x * (2.0f * p1 + p0);
        const float xrr = Em.x * Em.z + Em.y * Em.w;
        const float xri = Em.y * Em.z - Em.x * Em.w;
        c0r += w12.y * xrr;
        c0i += w12.y * xri;

        if (TB.h_start[mi] == TB.h_start[mi + 1]) continue;
        float g0r = 0.f, g0i = 0.f, g1r = 0.f, g1i = 0.f;
#pragma unroll
        for (int h = TB.h_start[mi]; h < TB.h_start[mi + 1]; ++h) {
            const int nn = TB.n_of_h[h];
            const float4 xn = xb[PP + nn];
            const float4 xs = xb[mi + nn];
            const float Sr = xn.x * xs.x + xn.y * xs.y + xn.z * xs.z + xn.w * xs.w;
            const float Si = xn.y * xs.x - xn.x * xs.y + xn.w * xs.z - xn.z * xs.w;
            const float4 w = shw[h];
            g0r += Sr * w.x - Si * w.y;
            g0i += Sr * w.y + Si * w.x;
            g1r += Sr * w.z - Si * w.w;
            g1i += Sr * w.w + Si * w.z;
        }
        E0r += g0r * Em.x - g0i * Em.y;
        E0i += g0r * Em.y + g0i * Em.x;
        E1r += g1r * Em.z - g1i * Em.w;
        E1i += g1r * Em.w + g1i * Em.z;
    }

    const long long tix = (long long)b * 4;
    const float ti0 = (tix < ti_sz) ? task_info[tix] : 0.0f;
    const float P   = 0.5f * exp10f(ti0 * 0.1f);
    const float c00 = (c00_sz > 0) ? C00[0] : 0.0f;
    const float pwp = xp.x * xp.x + xp.y * xp.y + xp.z * xp.z + xp.w * xp.w;
    const float phi0 = P * (c00 * pwp + 2.0f * ph0);
    const float phi1 = P * (c00 * pwp + 2.0f * ph1);
    float s0, cs0, s1, cs1;
    sincosf(phi0, &s0, &cs0);
    sincosf(phi1, &s1, &cs1);

    const float t0r = -(xp.z * c0i + xp.w * c0r);
    const float t0i =  (xp.z * c0r - xp.w * c0i);
    const float t1r =  (xp.x * c0i - xp.y * c0r);
    const float t1i =  (xp.x * c0r + xp.y * c0i);

    const float o0 = P * (E0r + t0r) + (xp.x * cs0 - xp.y * s0);  // re(b,0)
    const float o1 = P * (E0i + t0i) + (xp.x * s0 + xp.y * cs0);  // im(b,0)
    const float o2 = P * (E1r + t1r) + (xp.z * cs1 - xp.w * s1);  // re(b,1)
    const float o3 = P * (E1i + t1i) + (xp.z * s1 + xp.w * cs1);  // im(b,1)

    // ---- PLANAR layout: re-block then im-block, each (B,2) C-order ----
    // float2 view: re-block element b = (re0, re1); im-block element B+b.
    const long long reIdx = 2LL * b;              // floats
    const long long imIdx = 2LL * B + 2LL * b;    // floats
    if (imIdx + 1 < out_floats) {
        float2* __restrict__ out2 = (float2*)out;
        out2[b]     = make_float2(o0, o2);        // coalesced STG.64
        out2[B + b] = make_float2(o1, o3);
    } else {                                       // degenerate-capacity fallback
        if (reIdx     < out_floats) out[reIdx]     = o0;
        if (reIdx + 1 < out_floats) out[reIdx + 1] = o2;
        if (imIdx     < out_floats) out[imIdx]     = o1;
        if (imIdx + 1 < out_floats) out[imIdx + 1] = o3;
    }
}

extern "C" void kernel_launch(void* const* d_in, const int* in_sizes, int n_in,
                              void* d_out, int out_size)
{
    if (n_in < 8) return;

    bool has41 = false, has164 = false;
    for (int i = 0; i < n_in; ++i) {
        if (in_sizes[i] == 41)  has41 = true;
        if (in_sizes[i] == 164) has164 = true;
    }
    int div = 1;
    if (has41)       div = 1;
    else if (has164) div = 4;
    else return;

    long long es[64];
    const int ni = n_in < 64 ? n_in : 64;
    long long mx = 0;
    for (int i = 0; i < ni; ++i) {
        es[i] = (long long)in_sizes[i] / div;
        if (es[i] > mx) mx = es[i];
    }
    const long long Bll = mx / (MM * 2);
    if (Bll <= 0 || Bll * (MM * 2) != mx) return;

    // Dict-order binding (Path A; confirmed executing R10-R14).
    int ixr = 0, ixi = 1, iti = 2, ic00 = 3, iwr = 4, iwi = 5, ic1 = 6, ic2 = 7;
    bool pos_ok =
           es[0] == Bll * MM * 2 && es[1] == Bll * MM * 2
        && es[2] == Bll * 4      && es[3] == 1
        && es[4] == 2 * HDIM     && es[5] == 2 * HDIM
        && es[6] == MM           && es[7] == MM;

    if (!pos_ok) {
        ixr = ixi = iti = ic00 = iwr = iwi = ic1 = ic2 = -1;
        for (int i = 0; i < ni; ++i) {
            const long long s = es[i];
            if (s == mx)            { if (ixr < 0) ixr = i; else ixi = i; }
            else if (s == 1)        { ic00 = i; }
            else if (s == 2 * HDIM) { if (iwr < 0) iwr = i; else iwi = i; }
            else if (s == MM)       { if (ic1 < 0) ic1 = i; else ic2 = i; }
            else if (s == Bll * 4)  { iti = i; }
        }
        if (ixr < 0 || ixi < 0 || iti < 0 || ic00 < 0 ||
            iwr < 0 || iwi < 0 || ic1 < 0 || ic2 < 0)
            return;
    }

    const int B = (int)Bll;
    const long long want = (long long)B * 4;
    long long cap = (long long)out_size / div;
    long long out_floats = want < cap ? want : cap;

    const int grid = (B + NB - 1) / NB;
    eqampbc_kernel<<<grid, TPB>>>(
        (const float*)d_in[ixr], es[ixr],
        (const float*)d_in[ixi], es[ixi],
        (const float*)d_in[iti], es[iti],
        (const float*)d_in[ic00], es[ic00],
        (const float*)d_in[iwr], es[iwr],
        (const float*)d_in[iwi], es[iwi],
        (const float*)d_in[ic1], es[ic1],
        (const float*)d_in[ic2], es[ic2],
        (float*)d_out, out_floats, B);
}